// round 9
// baseline (speedup 1.0000x reference)
#include <cuda_runtime.h>
#include <cuda_fp16.h>
#include <math.h>
#include <stdint.h>

#define NR 8192
#define DD 128
#define ALPHA 2.0f
#define EXPBIAS 96.0f

// ---------------- device globals ----------------
__device__ __align__(128) __half g_au_h[NR * DD];
__device__ __align__(128) __half g_tp_h[NR * DD];
__device__ float g_pos[NR];    // sum_{j!=i} exp(s_aa-B) + exp(s_tt-B)
__device__ float g_neg[NR];    // sum_{j!=i} exp(s_at-B)
__device__ double g_supcon;
__device__ double g_pt;
__device__ unsigned g_done;

// ---------------- convert (+zero) kernel: 4 elems/thread ----------------
__global__ void esup_split_kernel(const float* __restrict__ z_au,
                                  const float* __restrict__ z_tp) {
    const int t4 = blockIdx.x * blockDim.x + threadIdx.x;   // 0..262143
    const int base = t4 * 4;
    if (t4 < NR) { g_pos[t4] = 0.0f; g_neg[t4] = 0.0f; }
    if (t4 == 0) { g_supcon = 0.0; g_pt = 0.0; g_done = 0u; }

    const float4 a = *(const float4*)(z_au + base);
    const float4 b = *(const float4*)(z_tp + base);
    ((__half2*)(g_au_h + base))[0] = __floats2half2_rn(a.x, a.y);
    ((__half2*)(g_au_h + base))[1] = __floats2half2_rn(a.z, a.w);
    ((__half2*)(g_tp_h + base))[0] = __floats2half2_rn(b.x, b.y);
    ((__half2*)(g_tp_h + base))[1] = __floats2half2_rn(b.z, b.w);
}

// ---------------- PTX helpers (baseline ISA, compiles at compute_103) ----------------
__device__ __forceinline__ uint32_t smem_u32(const void* p) {
    uint32_t a;
    asm("{ .reg .u64 t; cvta.to.shared.u64 t, %1; cvt.u32.u64 %0, t; }" : "=r"(a) : "l"(p));
    return a;
}

#define CP_ASYNC16(dst_u32, src_ptr) \
    asm volatile("cp.async.cg.shared.global [%0], [%1], 16;" \
        :: "r"(dst_u32), "l"(src_ptr) : "memory")

// mbarrier (sm_80 baseline)
#define MBAR_INIT(addr, cnt) \
    asm volatile("mbarrier.init.shared.b64 [%0], %1;" :: "r"((uint32_t)(addr)), "r"((uint32_t)(cnt)) : "memory")
#define MBAR_ARRIVE(addr) \
    asm volatile("mbarrier.arrive.shared.b64 _, [%0];" :: "r"((uint32_t)(addr)) : "memory")
#define CP_ARRIVE_NOINC(addr) \
    asm volatile("cp.async.mbarrier.arrive.noinc.shared.b64 [%0];" :: "r"((uint32_t)(addr)) : "memory")
#define MBAR_WAIT(addr, par) do {                                                 \
    uint32_t _m = (uint32_t)(addr); uint32_t _p = (uint32_t)(par); uint32_t _d;   \
    asm volatile("{\n\t.reg .pred p;\n\t"                                         \
        "mbarrier.try_wait.parity.shared.b64 p, [%1], %2;\n\t"                    \
        "selp.b32 %0, 1, 0, p;\n\t}"                                              \
        : "=r"(_d) : "r"(_m), "r"(_p) : "memory");                                \
    if (!_d) {                                                                    \
        asm volatile("{\n\t.reg .pred P1;\n\t"                                    \
            "WL_%=:\n\t"                                                          \
            "mbarrier.try_wait.parity.shared.b64 P1, [%0], %1;\n\t"               \
            "@P1 bra.uni WD_%=;\n\t"                                              \
            "bra.uni WL_%=;\n\t"                                                  \
            "WD_%=:\n\t}" :: "r"(_m), "r"(_p) : "memory");                        \
    }                                                                             \
} while (0)

__device__ __forceinline__ void ldsm_x4(uint32_t* r, uint32_t addr) {
    asm volatile("ldmatrix.sync.aligned.m8n8.x4.shared.b16 {%0,%1,%2,%3}, [%4];"
        : "=r"(r[0]), "=r"(r[1]), "=r"(r[2]), "=r"(r[3]) : "r"(addr));
}

__device__ __forceinline__ void mma16816(float* c, const uint32_t* a,
                                         uint32_t b0, uint32_t b1) {
    asm volatile("mma.sync.aligned.m16n8k16.row.col.f32.f16.f16.f32 "
        "{%0,%1,%2,%3}, {%4,%5,%6,%7}, {%8,%9}, {%0,%1,%2,%3};"
        : "+f"(c[0]), "+f"(c[1]), "+f"(c[2]), "+f"(c[3])
        : "r"(a[0]), "r"(a[1]), "r"(a[2]), "r"(a[3]), "r"(b0), "r"(b1));
}

// exp(v - EXPBIAS) via single ex2.approx; 138.4987239... = 96 * log2(e)
__device__ __forceinline__ float fexp_b(float v) {
    float r;
    const float t = fmaf(v, 1.4426950408889634f, -138.4987239052529f);
    asm("ex2.approx.f32 %0, %1;" : "=f"(r) : "f"(t));
    return r;
}

// smem tile: [128 rows][16 chunks of 16B], chunk xor-swizzled by (row & 7)
__device__ __forceinline__ uint32_t tile_off(int row, int c) {
    return (uint32_t)(row * 256 + ((c ^ (row & 7)) << 4));
}

// ---------------- main fused GEMM + exp-sum kernel ----------------
// smem: A [0,32K); B stage s at 32K + s*32K (3 stages); scol at 128K; mbars after.
#define SM_A    0u
#define SM_B    32768u
#define SM_COL  131072u
#define SM_MBAR 133120u     // full0/1/2 at +0/8/16, empty0/1/2 at +24/32/40
#define SMEM_BYTES 133184

// grid layout: [0,544) job aa triangular, [544,1088) job tt triangular,
// [1088,2112) job at rectangular (64 row tiles x 16 chunks of 4 col tiles)
__global__ __launch_bounds__(256, 1) void esup_mma_kernel() {
    extern __shared__ char smem[];
    const uint32_t sb = smem_u32(smem);
    float* scol = (float*)(smem + SM_COL);       // [512]
    const int tid = threadIdx.x;
    const int lane = tid & 31;
    const int wid = tid >> 5;
    const int wrow = wid & 3;        // 4 warp-rows of 32
    const int wcol = wid >> 2;       // 2 warp-cols of 64

    // ---- bid -> (job, row tile it, chunk) ----
    int job, it, chunk;
    {
        const int bid = blockIdx.x;
        if (bid < 1088) {
            job = (bid < 544) ? 0 : 1;
            int s = (bid < 544) ? bid : bid - 544;
            int itv = 0;
            while (true) {
                const int w = 16 - (itv >> 2);
                if (s < w) break;
                s -= w; ++itv;
            }
            it = itv;
            chunk = (it >> 2) + s;
        } else {
            job = 2;
            const int r = bid - 1088;
            it = r >> 4;
            chunk = r & 15;
        }
    }
    const int i0 = it * 128;
    const int j0base = chunk * 512;

    const __half *Ahi_g, *Bhi_g;
    if (job == 0)      { Ahi_g = g_au_h; Bhi_g = g_au_h; }
    else if (job == 1) { Ahi_g = g_tp_h; Bhi_g = g_tp_h; }
    else               { Ahi_g = g_au_h; Bhi_g = g_tp_h; }

    // mbarrier init + scol zero
    if (tid == 0) {
        MBAR_INIT(sb + SM_MBAR + 0,  256);   // full0
        MBAR_INIT(sb + SM_MBAR + 8,  256);   // full1
        MBAR_INIT(sb + SM_MBAR + 16, 256);   // full2
        MBAR_INIT(sb + SM_MBAR + 24, 256);   // empty0
        MBAR_INIT(sb + SM_MBAR + 32, 256);   // empty1
        MBAR_INIT(sb + SM_MBAR + 40, 256);   // empty2
    }
    if (job != 2) {
        scol[tid] = 0.0f;
        scol[tid + 256] = 0.0f;
    }
    __syncthreads();

    // ---- prologue: A tile + B tile 0 -> full0 ; B tile 1 -> full1 ----
    #pragma unroll
    for (int itr = 0; itr < 8; ++itr) {
        const int idx = tid + itr * 256;             // 0..2047
        const int row = idx >> 4, c = idx & 15;
        CP_ASYNC16(sb + SM_A + tile_off(row, c),
                   Ahi_g + (size_t)(i0 + row) * DD + c * 8);
    }
    #pragma unroll
    for (int itr = 0; itr < 8; ++itr) {
        const int idx = tid + itr * 256;
        const int row = idx >> 4, c = idx & 15;
        CP_ASYNC16(sb + SM_B + tile_off(row, c),
                   Bhi_g + (size_t)(j0base + row) * DD + c * 8);
    }
    CP_ARRIVE_NOINC(sb + SM_MBAR + 0);
    #pragma unroll
    for (int itr = 0; itr < 8; ++itr) {
        const int idx = tid + itr * 256;
        const int row = idx >> 4, c = idx & 15;
        CP_ASYNC16(sb + SM_B + 32768u + tile_off(row, c),
                   Bhi_g + (size_t)(j0base + 128 + row) * DD + c * 8);
    }
    CP_ARRIVE_NOINC(sb + SM_MBAR + 8);

    // persistent per-thread row exp-sums: [mt][rh]
    float rs[2][2] = {{0.f, 0.f}, {0.f, 0.f}};

    // hoisted fragment addressing bases
    const int arow0 = wrow * 32 + (lane & 15);
    const int bn0 = wcol * 64 + ((lane >> 4) << 3) + (lane & 7);

    // A fragments: resident in registers for the whole j-loop (64 regs)
    uint32_t Afrag[8][2][4];

    #pragma unroll
    for (int t = 0; t < 4; ++t) {
        // issue fill for tile t+2 (stage (t+2)%3)
        if (t + 2 < 4) {
            const int u = t + 2;
            if (u >= 3) MBAR_WAIT(sb + SM_MBAR + 24 + ((u % 3) * 8), 0);   // empty, phase 0
            const uint32_t stg = sb + SM_B + (uint32_t)(u % 3) * 32768u;
            const int j0n = j0base + u * 128;
            #pragma unroll
            for (int itr = 0; itr < 8; ++itr) {
                const int idx = tid + itr * 256;
                const int row = idx >> 4, c = idx & 15;
                CP_ASYNC16(stg + tile_off(row, c),
                           Bhi_g + (size_t)(j0n + row) * DD + c * 8);
            }
            CP_ARRIVE_NOINC(sb + SM_MBAR + (u % 3) * 8);
        }

        // wait current stage full (stage t%3; phase flips after first wrap)
        MBAR_WAIT(sb + SM_MBAR + (t % 3) * 8, (t < 3) ? 0 : 1);

        // load A fragments once (after full0: A arrived with stage 0)
        if (t == 0) {
            #pragma unroll
            for (int ks = 0; ks < 8; ++ks) {
                const int ac = ks * 2 + (lane >> 4);
                #pragma unroll
                for (int mt = 0; mt < 2; ++mt)
                    ldsm_x4(Afrag[ks][mt], sb + SM_A + tile_off(arow0 + mt * 16, ac));
            }
        }

        const uint32_t bsb = sb + SM_B + (uint32_t)(t % 3) * 32768u;
        const int j0 = j0base + t * 128;
        const int jt = chunk * 4 + t;

        float acc[2][8][4];
        #pragma unroll
        for (int mt = 0; mt < 2; ++mt)
            #pragma unroll
            for (int nt = 0; nt < 8; ++nt)
                #pragma unroll
                for (int q = 0; q < 4; ++q) acc[mt][nt][q] = 0.f;

        #pragma unroll
        for (int ks = 0; ks < 8; ++ks) {
            const int bc = ks * 2 + ((lane >> 3) & 1);
            #pragma unroll
            for (int nt2 = 0; nt2 < 4; ++nt2) {
                uint32_t Bh[4];                               // live briefly
                ldsm_x4(Bh, bsb + tile_off(bn0 + nt2 * 16, bc));
                #pragma unroll
                for (int mt = 0; mt < 2; ++mt) {
                    mma16816(acc[mt][nt2 * 2 + 0], Afrag[ks][mt], Bh[0], Bh[1]);
                    mma16816(acc[mt][nt2 * 2 + 1], Afrag[ks][mt], Bh[2], Bh[3]);
                }
            }
        }
        // stage consumed: free it for producers
        MBAR_ARRIVE(sb + SM_MBAR + 24 + (t % 3) * 8);

        // ---- epilogue (no CTA barrier) ----
        if (job != 2 && jt > it) {
            // strictly upper triangular: row + column sums, no diag mask
            #pragma unroll
            for (int nt = 0; nt < 8; ++nt) {
                float c0 = 0.f, c1 = 0.f;
                #pragma unroll
                for (int mt = 0; mt < 2; ++mt) {
                    #pragma unroll
                    for (int rh = 0; rh < 2; ++rh) {
                        const float e0 = fexp_b(acc[mt][nt][rh * 2 + 0]);
                        const float e1 = fexp_b(acc[mt][nt][rh * 2 + 1]);
                        rs[mt][rh] += e0 + e1;
                        c0 += e0; c1 += e1;
                    }
                }
                // reduce over the 8 lanes sharing (lane & 3): bits 2..4
                c0 += __shfl_xor_sync(0xFFFFFFFF, c0, 4);
                c0 += __shfl_xor_sync(0xFFFFFFFF, c0, 8);
                c0 += __shfl_xor_sync(0xFFFFFFFF, c0, 16);
                c1 += __shfl_xor_sync(0xFFFFFFFF, c1, 4);
                c1 += __shfl_xor_sync(0xFFFFFFFF, c1, 8);
                c1 += __shfl_xor_sync(0xFFFFFFFF, c1, 16);
                if (lane < 4) {
                    const int lc = t * 128 + wcol * 64 + nt * 8 + lane * 2;
                    atomicAdd(&scol[lc], c0);
                    atomicAdd(&scol[lc + 1], c1);
                }
            }
        } else if (job == 2 || jt == it) {
            // row-only path (at job, or diagonal tiles of symmetric jobs)
            const bool dt = (jt == it);
            #pragma unroll
            for (int nt = 0; nt < 8; ++nt) {
                #pragma unroll
                for (int mt = 0; mt < 2; ++mt) {
                    #pragma unroll
                    for (int rh = 0; rh < 2; ++rh) {
                        float v0 = acc[mt][nt][rh * 2 + 0];
                        float v1 = acc[mt][nt][rh * 2 + 1];
                        if (dt) {
                            const int gr = i0 + wrow * 32 + mt * 16 + rh * 8 + (lane >> 2);
                            const int gc0 = j0 + wcol * 64 + nt * 8 + (lane & 3) * 2;
                            if (gr == gc0) v0 = -1e30f;
                            if (gr == gc0 + 1) v1 = -1e30f;
                        }
                        rs[mt][rh] += fexp_b(v0) + fexp_b(v1);
                    }
                }
            }
        }
        // jt < it on symmetric jobs: tile discarded (covered by transpose)
    }

    // ---- row flush: quad reduce + global atomics ----
    float* dst = (job == 2) ? g_neg : g_pos;
    #pragma unroll
    for (int mt = 0; mt < 2; ++mt) {
        #pragma unroll
        for (int rh = 0; rh < 2; ++rh) {
            float s = rs[mt][rh];
            s += __shfl_xor_sync(0xFFFFFFFF, s, 1);
            s += __shfl_xor_sync(0xFFFFFFFF, s, 2);
            if ((lane & 3) == 0) {
                const int gr = i0 + wrow * 32 + mt * 16 + rh * 8 + (lane >> 2);
                atomicAdd(dst + gr, s);
            }
        }
    }

    // ---- column flush (symmetric jobs: transpose contribution) ----
    if (job != 2) {
        __syncthreads();
        #pragma unroll
        for (int q = 0; q < 2; ++q) {
            const int idx = tid + q * 256;
            const float v = scol[idx];
            if (v != 0.0f) atomicAdd(&g_pos[j0base + idx], v);
        }
    }
}

// ---------------- per-row reduction (+ fused finalize) ----------------
__global__ void esup_rowreduce_kernel(const float* __restrict__ z_au,
                                      const float* __restrict__ z_tp,
                                      const float* __restrict__ fc,
                                      float* __restrict__ out) {
    __shared__ float sv[8], sp[8];
    const int lane = threadIdx.x & 31;
    const int wid = threadIdx.x >> 5;
    const int row = blockIdx.x * 8 + wid;

    const float4 a = *(const float4*)(z_au + (size_t)row * DD + lane * 4);
    const float4 b = *(const float4*)(z_tp + (size_t)row * DD + lane * 4);
    const float4 w0 = *(const float4*)(fc + lane * 4);
    const float4 w1 = *(const float4*)(fc + DD + lane * 4);

    float diag = a.x * b.x + a.y * b.y + a.z * b.z + a.w * b.w;
    float pt = (a.x - b.x) * (w1.x - w0.x) + (a.y - b.y) * (w1.y - w0.y) +
               (a.z - b.z) * (w1.z - w0.z) + (a.w - b.w) * (w1.w - w0.w);
    #pragma unroll
    for (int s = 16; s > 0; s >>= 1) {
        diag += __shfl_xor_sync(0xFFFFFFFF, diag, s);
        pt   += __shfl_xor_sync(0xFFFFFFFF, pt, s);
    }
    if (lane == 0) {
        const float pos = EXPBIAS + logf(g_pos[row]);
        const float neg = EXPBIAS + logf(g_neg[row]);
        sv[wid] = -pos + neg + ALPHA * diag;
        sp[wid] = pt;
    }
    __syncthreads();
    if (threadIdx.x == 0) {
        double s = 0.0, p = 0.0;
        #pragma unroll
        for (int i = 0; i < 8; ++i) { s += (double)sv[i]; p += (double)sp[i]; }
        atomicAdd(&g_supcon, s);
        atomicAdd(&g_pt, p);
        __threadfence();
        const unsigned prev = atomicAdd(&g_done, 1u);
        if (prev == gridDim.x - 1) {
            const double st = atomicAdd(&g_supcon, 0.0);
            const double pp = atomicAdd(&g_pt, 0.0);
            out[0] = (float)((pp / (double)NR + st) / (double)(NR + 2));
        }
    }
}

// ---------------- launch ----------------
extern "C" void kernel_launch(void* const* d_in, const int* in_sizes, int n_in,
                              void* d_out, int out_size) {
    const float* z_au = (const float*)d_in[0];
    const float* z_tp = (const float*)d_in[1];
    const float* fc   = (const float*)d_in[2];
    float* out = (float*)d_out;

    cudaFuncSetAttribute(esup_mma_kernel,
                         cudaFuncAttributeMaxDynamicSharedMemorySize, SMEM_BYTES);

    esup_split_kernel<<<(NR * DD / 4) / 256, 256>>>(z_au, z_tp);
    esup_mma_kernel<<<2112, 256, SMEM_BYTES>>>();
    esup_rowreduce_kernel<<<NR / 8, 256>>>(z_au, z_tp, fc, out);
}

// round 10
// speedup vs baseline: 1.0534x; 1.0534x over previous
#include <cuda_runtime.h>
#include <cuda_fp16.h>
#include <math.h>
#include <stdint.h>

#define NR 8192
#define DD 128
#define ALPHA 2.0f
#define EXPBIAS 96.0f

// ---------------- device globals ----------------
__device__ __align__(128) __half g_au_h[NR * DD];
__device__ __align__(128) __half g_tp_h[NR * DD];
__device__ float g_pos[NR];    // sum_{j!=i} exp(s_aa-B) + exp(s_tt-B)
__device__ float g_neg[NR];    // sum_{j!=i} exp(s_at-B)
__device__ double g_supcon;
__device__ double g_pt;
__device__ unsigned g_done;

// ---------------- convert (+zero) kernel: 4 elems/thread ----------------
__global__ void esup_split_kernel(const float* __restrict__ z_au,
                                  const float* __restrict__ z_tp) {
    const int t4 = blockIdx.x * blockDim.x + threadIdx.x;   // 0..262143
    const int base = t4 * 4;
    if (t4 < NR) { g_pos[t4] = 0.0f; g_neg[t4] = 0.0f; }
    if (t4 == 0) { g_supcon = 0.0; g_pt = 0.0; g_done = 0u; }

    const float4 a = *(const float4*)(z_au + base);
    const float4 b = *(const float4*)(z_tp + base);
    ((__half2*)(g_au_h + base))[0] = __floats2half2_rn(a.x, a.y);
    ((__half2*)(g_au_h + base))[1] = __floats2half2_rn(a.z, a.w);
    ((__half2*)(g_tp_h + base))[0] = __floats2half2_rn(b.x, b.y);
    ((__half2*)(g_tp_h + base))[1] = __floats2half2_rn(b.z, b.w);
}

// ---------------- PTX helpers (baseline ISA, compiles at compute_103) ----------------
__device__ __forceinline__ uint32_t smem_u32(const void* p) {
    uint32_t a;
    asm("{ .reg .u64 t; cvta.to.shared.u64 t, %1; cvt.u32.u64 %0, t; }" : "=r"(a) : "l"(p));
    return a;
}

#define CP_ASYNC16(dst_u32, src_ptr) \
    asm volatile("cp.async.cg.shared.global [%0], [%1], 16;" \
        :: "r"(dst_u32), "l"(src_ptr) : "memory")

// mbarrier (sm_80 baseline)
#define MBAR_INIT(addr, cnt) \
    asm volatile("mbarrier.init.shared.b64 [%0], %1;" :: "r"((uint32_t)(addr)), "r"((uint32_t)(cnt)) : "memory")
#define CP_ARRIVE_NOINC(addr) \
    asm volatile("cp.async.mbarrier.arrive.noinc.shared.b64 [%0];" :: "r"((uint32_t)(addr)) : "memory")
#define MBAR_WAIT(addr, par) do {                                                 \
    uint32_t _m = (uint32_t)(addr); uint32_t _p = (uint32_t)(par); uint32_t _d;   \
    asm volatile("{\n\t.reg .pred p;\n\t"                                         \
        "mbarrier.try_wait.parity.shared.b64 p, [%1], %2;\n\t"                    \
        "selp.b32 %0, 1, 0, p;\n\t}"                                              \
        : "=r"(_d) : "r"(_m), "r"(_p) : "memory");                                \
    if (!_d) {                                                                    \
        asm volatile("{\n\t.reg .pred P1;\n\t"                                    \
            "WL_%=:\n\t"                                                          \
            "mbarrier.try_wait.parity.shared.b64 P1, [%0], %1;\n\t"               \
            "@P1 bra.uni WD_%=;\n\t"                                              \
            "bra.uni WL_%=;\n\t"                                                  \
            "WD_%=:\n\t}" :: "r"(_m), "r"(_p) : "memory");                        \
    }                                                                             \
} while (0)

__device__ __forceinline__ void ldsm_x4(uint32_t* r, uint32_t addr) {
    asm volatile("ldmatrix.sync.aligned.m8n8.x4.shared.b16 {%0,%1,%2,%3}, [%4];"
        : "=r"(r[0]), "=r"(r[1]), "=r"(r[2]), "=r"(r[3]) : "r"(addr));
}

__device__ __forceinline__ void mma16816(float* c, const uint32_t* a,
                                         uint32_t b0, uint32_t b1) {
    asm volatile("mma.sync.aligned.m16n8k16.row.col.f32.f16.f16.f32 "
        "{%0,%1,%2,%3}, {%4,%5,%6,%7}, {%8,%9}, {%0,%1,%2,%3};"
        : "+f"(c[0]), "+f"(c[1]), "+f"(c[2]), "+f"(c[3])
        : "r"(a[0]), "r"(a[1]), "r"(a[2]), "r"(a[3]), "r"(b0), "r"(b1));
}

// exp(v - EXPBIAS) via single ex2.approx; 138.4987239... = 96 * log2(e)
__device__ __forceinline__ float fexp_b(float v) {
    float r;
    const float t = fmaf(v, 1.4426950408889634f, -138.4987239052529f);
    asm("ex2.approx.f32 %0, %1;" : "=f"(r) : "f"(t));
    return r;
}

// smem tile: [rows][16 chunks of 16B], chunk xor-swizzled by (row & 7)
__device__ __forceinline__ uint32_t tile_off(int row, int c) {
    return (uint32_t)(row * 256 + ((c ^ (row & 7)) << 4));
}

// ---------------- main fused GEMM + exp-sum kernel ----------------
// smem: A [0,32K); B stage0 [32K,96K); B stage1 [96K,160K); scol at 160K; mbars.
#define SM_A    0u
#define SM_B    32768u
#define SM_COL  163840u
#define SM_MBAR 165888u     // full0 at +0, full1 at +8
#define SMEM_BYTES 165952

// grid layout: [0,544) job aa triangular, [544,1088) job tt triangular,
// [1088,2112) job at rectangular (64 row tiles x 16 chunks of 4 col blocks)
// Each CTA: 128 rows x 512 cols, processed as two 128x256 t-iterations.
__global__ __launch_bounds__(256, 1) void esup_mma_kernel() {
    extern __shared__ char smem[];
    const uint32_t sb = smem_u32(smem);
    float* scol = (float*)(smem + SM_COL);       // [512]
    const int tid = threadIdx.x;
    const int lane = tid & 31;
    const int wid = tid >> 5;
    const int wrow = wid >> 2;       // 2 warp-rows of 64
    const int wcol = wid & 3;        // 4 warp-cols of 64

    // ---- bid -> (job, row tile it, chunk) ----
    int job, it, chunk;
    {
        const int bid = blockIdx.x;
        if (bid < 1088) {
            job = (bid < 544) ? 0 : 1;
            int s = (bid < 544) ? bid : bid - 544;
            int itv = 0;
            while (true) {
                const int w = 16 - (itv >> 2);
                if (s < w) break;
                s -= w; ++itv;
            }
            it = itv;
            chunk = (it >> 2) + s;
        } else {
            job = 2;
            const int r = bid - 1088;
            it = r >> 4;
            chunk = r & 15;
        }
    }
    const int i0 = it * 128;
    const int j0base = chunk * 512;

    const __half *Ahi_g, *Bhi_g;
    if (job == 0)      { Ahi_g = g_au_h; Bhi_g = g_au_h; }
    else if (job == 1) { Ahi_g = g_tp_h; Bhi_g = g_tp_h; }
    else               { Ahi_g = g_au_h; Bhi_g = g_tp_h; }

    if (tid == 0) {
        MBAR_INIT(sb + SM_MBAR + 0, 256);   // full0
        MBAR_INIT(sb + SM_MBAR + 8, 256);   // full1
    }
    if (job != 2) {
        scol[tid] = 0.0f;
        scol[tid + 256] = 0.0f;
    }
    __syncthreads();

    // ---- prologue: everything prefilled, no in-loop pipeline ----
    #pragma unroll
    for (int itr = 0; itr < 8; ++itr) {                 // A: 128x128
        const int idx = tid + itr * 256;                // 0..2047
        const int row = idx >> 4, c = idx & 15;
        CP_ASYNC16(sb + SM_A + tile_off(row, c),
                   Ahi_g + (size_t)(i0 + row) * DD + c * 8);
    }
    #pragma unroll
    for (int itr = 0; itr < 16; ++itr) {                // B0: 256x128
        const int idx = tid + itr * 256;                // 0..4095
        const int row = idx >> 4, c = idx & 15;
        CP_ASYNC16(sb + SM_B + tile_off(row, c),
                   Bhi_g + (size_t)(j0base + row) * DD + c * 8);
    }
    CP_ARRIVE_NOINC(sb + SM_MBAR + 0);
    #pragma unroll
    for (int itr = 0; itr < 16; ++itr) {                // B1: next 256 cols
        const int idx = tid + itr * 256;
        const int row = idx >> 4, c = idx & 15;
        CP_ASYNC16(sb + SM_B + 65536u + tile_off(row, c),
                   Bhi_g + (size_t)(j0base + 256 + row) * DD + c * 8);
    }
    CP_ARRIVE_NOINC(sb + SM_MBAR + 8);

    // persistent per-thread row exp-sums: [mt][rh]
    float rs[4][2];
    #pragma unroll
    for (int mt = 0; mt < 4; ++mt) { rs[mt][0] = 0.f; rs[mt][1] = 0.f; }

    const int arow0 = wrow * 64 + (lane & 15);
    const int bn0 = wcol * 64 + ((lane >> 4) << 3) + (lane & 7);

    for (int t = 0; t < 2; ++t) {
        MBAR_WAIT(sb + SM_MBAR + t * 8, 0);
        const uint32_t bsb = sb + SM_B + (uint32_t)t * 65536u;

        float acc[4][8][4];
        #pragma unroll
        for (int mt = 0; mt < 4; ++mt)
            #pragma unroll
            for (int nt = 0; nt < 8; ++nt)
                #pragma unroll
                for (int q = 0; q < 4; ++q) acc[mt][nt][q] = 0.f;

        #pragma unroll
        for (int ks = 0; ks < 8; ++ks) {
            uint32_t Ah[4][4];
            const int ac = ks * 2 + (lane >> 4);
            #pragma unroll
            for (int mt = 0; mt < 4; ++mt)
                ldsm_x4(Ah[mt], sb + SM_A + tile_off(arow0 + mt * 16, ac));

            const int bc = ks * 2 + ((lane >> 3) & 1);
            #pragma unroll
            for (int nt2 = 0; nt2 < 4; ++nt2) {
                uint32_t Bh[4];
                ldsm_x4(Bh, bsb + tile_off(bn0 + nt2 * 16, bc));
                #pragma unroll
                for (int mt = 0; mt < 4; ++mt) {
                    mma16816(acc[mt][nt2 * 2 + 0], Ah[mt], Bh[0], Bh[1]);
                    mma16816(acc[mt][nt2 * 2 + 1], Ah[mt], Bh[2], Bh[3]);
                }
            }
        }

        // ---- epilogue; this warp's 128-col block index ----
        const int jt = chunk * 4 + t * 2 + (wcol >> 1);
        if (job != 2 && jt > it) {
            // strictly upper triangular: row + column sums, no diag mask
            #pragma unroll
            for (int nt = 0; nt < 8; ++nt) {
                float c0 = 0.f, c1 = 0.f;
                #pragma unroll
                for (int mt = 0; mt < 4; ++mt) {
                    #pragma unroll
                    for (int rh = 0; rh < 2; ++rh) {
                        const float e0 = fexp_b(acc[mt][nt][rh * 2 + 0]);
                        const float e1 = fexp_b(acc[mt][nt][rh * 2 + 1]);
                        rs[mt][rh] += e0 + e1;
                        c0 += e0; c1 += e1;
                    }
                }
                // reduce over the 8 lanes sharing (lane & 3): bits 2..4
                c0 += __shfl_xor_sync(0xFFFFFFFF, c0, 4);
                c0 += __shfl_xor_sync(0xFFFFFFFF, c0, 8);
                c0 += __shfl_xor_sync(0xFFFFFFFF, c0, 16);
                c1 += __shfl_xor_sync(0xFFFFFFFF, c1, 4);
                c1 += __shfl_xor_sync(0xFFFFFFFF, c1, 8);
                c1 += __shfl_xor_sync(0xFFFFFFFF, c1, 16);
                if (lane < 4) {
                    const int lc = t * 256 + wcol * 64 + nt * 8 + lane * 2;
                    atomicAdd(&scol[lc], c0);
                    atomicAdd(&scol[lc + 1], c1);
                }
            }
        } else if (job == 2 || jt == it) {
            // row-only path (at job, or diagonal blocks)
            const bool dt = (jt == it);
            const int gc_base = j0base + t * 256 + wcol * 64 + (lane & 3) * 2;
            const int gr_base = i0 + wrow * 64 + (lane >> 2);
            #pragma unroll
            for (int nt = 0; nt < 8; ++nt) {
                #pragma unroll
                for (int mt = 0; mt < 4; ++mt) {
                    #pragma unroll
                    for (int rh = 0; rh < 2; ++rh) {
                        float v0 = acc[mt][nt][rh * 2 + 0];
                        float v1 = acc[mt][nt][rh * 2 + 1];
                        if (dt) {
                            const int gr = gr_base + mt * 16 + rh * 8;
                            const int gc0 = gc_base + nt * 8;
                            if (gr == gc0) v0 = -1e30f;
                            if (gr == gc0 + 1) v1 = -1e30f;
                        }
                        rs[mt][rh] += fexp_b(v0) + fexp_b(v1);
                    }
                }
            }
        }
        // jt < it on symmetric jobs: block discarded (covered by transpose)
    }

    // ---- row flush: quad reduce + global atomics ----
    float* dst = (job == 2) ? g_neg : g_pos;
    #pragma unroll
    for (int mt = 0; mt < 4; ++mt) {
        #pragma unroll
        for (int rh = 0; rh < 2; ++rh) {
            float s = rs[mt][rh];
            s += __shfl_xor_sync(0xFFFFFFFF, s, 1);
            s += __shfl_xor_sync(0xFFFFFFFF, s, 2);
            if ((lane & 3) == 0) {
                const int gr = i0 + wrow * 64 + mt * 16 + rh * 8 + (lane >> 2);
                atomicAdd(dst + gr, s);
            }
        }
    }

    // ---- column flush (symmetric jobs: transpose contribution) ----
    if (job != 2) {
        __syncthreads();
        #pragma unroll
        for (int q = 0; q < 2; ++q) {
            const int idx = tid + q * 256;
            const float v = scol[idx];
            if (v != 0.0f) atomicAdd(&g_pos[j0base + idx], v);
        }
    }
}

// ---------------- per-row reduction (+ fused finalize) ----------------
__global__ void esup_rowreduce_kernel(const float* __restrict__ z_au,
                                      const float* __restrict__ z_tp,
                                      const float* __restrict__ fc,
                                      float* __restrict__ out) {
    __shared__ float sv[8], sp[8];
    const int lane = threadIdx.x & 31;
    const int wid = threadIdx.x >> 5;
    const int row = blockIdx.x * 8 + wid;

    const float4 a = *(const float4*)(z_au + (size_t)row * DD + lane * 4);
    const float4 b = *(const float4*)(z_tp + (size_t)row * DD + lane * 4);
    const float4 w0 = *(const float4*)(fc + lane * 4);
    const float4 w1 = *(const float4*)(fc + DD + lane * 4);

    float diag = a.x * b.x + a.y * b.y + a.z * b.z + a.w * b.w;
    float pt = (a.x - b.x) * (w1.x - w0.x) + (a.y - b.y) * (w1.y - w0.y) +
               (a.z - b.z) * (w1.z - w0.z) + (a.w - b.w) * (w1.w - w0.w);
    #pragma unroll
    for (int s = 16; s > 0; s >>= 1) {
        diag += __shfl_xor_sync(0xFFFFFFFF, diag, s);
        pt   += __shfl_xor_sync(0xFFFFFFFF, pt, s);
    }
    if (lane == 0) {
        const float pos = EXPBIAS + logf(g_pos[row]);
        const float neg = EXPBIAS + logf(g_neg[row]);
        sv[wid] = -pos + neg + ALPHA * diag;
        sp[wid] = pt;
    }
    __syncthreads();
    if (threadIdx.x == 0) {
        double s = 0.0, p = 0.0;
        #pragma unroll
        for (int i = 0; i < 8; ++i) { s += (double)sv[i]; p += (double)sp[i]; }
        atomicAdd(&g_supcon, s);
        atomicAdd(&g_pt, p);
        __threadfence();
        const unsigned prev = atomicAdd(&g_done, 1u);
        if (prev == gridDim.x - 1) {
            const double st = atomicAdd(&g_supcon, 0.0);
            const double pp = atomicAdd(&g_pt, 0.0);
            out[0] = (float)((pp / (double)NR + st) / (double)(NR + 2));
        }
    }
}

// ---------------- launch ----------------
extern "C" void kernel_launch(void* const* d_in, const int* in_sizes, int n_in,
                              void* d_out, int out_size) {
    const float* z_au = (const float*)d_in[0];
    const float* z_tp = (const float*)d_in[1];
    const float* fc   = (const float*)d_in[2];
    float* out = (float*)d_out;

    cudaFuncSetAttribute(esup_mma_kernel,
                         cudaFuncAttributeMaxDynamicSharedMemorySize, SMEM_BYTES);

    esup_split_kernel<<<(NR * DD / 4) / 256, 256>>>(z_au, z_tp);
    esup_mma_kernel<<<2112, 256, SMEM_BYTES>>>();
    esup_rowreduce_kernel<<<NR / 8, 256>>>(z_au, z_tp, fc, out);
}